// round 13
// baseline (speedup 1.0000x reference)
#include <cuda_runtime.h>
#include <cuda_bf16.h>
#include <cstdint>

// out[i] = 0.1 * x[i] * sum_j A[i][j] * (1 - x[j])
// HBM-bound fp32 matvec. Block-per-row: 8 warps/block, each warp streams one
// contiguous 1/8-row segment (8 KB, the proven sweet-spot task size) with
// evict-first LDG.128 at MLP=4. Partials combined via an 8-slot smem
// reduction and ONE plain store per row -> no atomics, no init kernel,
// single graph node. Grid = n = 16384 blocks (64 KB granularity, as R6).

#define WARPS_PER_BLOCK 8
#define THREADS (WARPS_PER_BLOCK * 32)

__global__ void __launch_bounds__(THREADS)
epidemic_matvec_kernel(const float* __restrict__ x,
                       const float* __restrict__ A,
                       float* __restrict__ out,
                       int n, int seg_len)
{
    __shared__ float warp_sum[WARPS_PER_BLOCK];

    const int tid  = threadIdx.x;
    const int warp = tid >> 5;
    const int lane = tid & 31;
    const int row  = blockIdx.x;
    if (row >= n) return;

    const int j0 = warp * seg_len;
    const int j1 = min(n, j0 + seg_len);

    const float* __restrict__ Arow = A + (size_t)row * (size_t)n;

    float s0 = 0.0f, s1 = 0.0f, s2 = 0.0f, s3 = 0.0f;

    if ((n & 3) == 0 && j0 < n) {
        // seg_len is a multiple of 8 -> segment bases stay 32B-aligned
        const float4* __restrict__ A4 = reinterpret_cast<const float4*>(Arow + j0);
        const float4* __restrict__ x4 = reinterpret_cast<const float4*>(x + j0);
        const int nv = (j1 - j0) >> 2;

        int k = lane;
        // Front-batch 4 independent streaming LDG.128 on A (MLP=4).
        // For n=16384: nv=512 -> exactly 4 iterations, no tails.
        for (; k + 96 < nv; k += 128) {
            float4 a0 = __ldcs(&A4[k]);
            float4 a1 = __ldcs(&A4[k + 32]);
            float4 a2 = __ldcs(&A4[k + 64]);
            float4 a3 = __ldcs(&A4[k + 96]);
            float4 b0 = x4[k];
            float4 b1 = x4[k + 32];
            float4 b2 = x4[k + 64];
            float4 b3 = x4[k + 96];
            s0 += a0.x * (1.0f - b0.x) + a0.y * (1.0f - b0.y)
                + a0.z * (1.0f - b0.z) + a0.w * (1.0f - b0.w);
            s1 += a1.x * (1.0f - b1.x) + a1.y * (1.0f - b1.y)
                + a1.z * (1.0f - b1.z) + a1.w * (1.0f - b1.w);
            s2 += a2.x * (1.0f - b2.x) + a2.y * (1.0f - b2.y)
                + a2.z * (1.0f - b2.z) + a2.w * (1.0f - b2.w);
            s3 += a3.x * (1.0f - b3.x) + a3.y * (1.0f - b3.y)
                + a3.z * (1.0f - b3.z) + a3.w * (1.0f - b3.w);
        }
        for (; k < nv; k += 32) {
            float4 a0 = __ldcs(&A4[k]);
            float4 b0 = x4[k];
            s0 += a0.x * (1.0f - b0.x) + a0.y * (1.0f - b0.y)
                + a0.z * (1.0f - b0.z) + a0.w * (1.0f - b0.w);
        }
        // scalar remainder within segment
        for (int j = j0 + (nv << 2) + lane; j < j1; j += 32)
            s0 += Arow[j] * (1.0f - x[j]);
    } else if (j0 < n) {
        // general scalar fallback
        for (int j = j0 + lane; j < j1; j += 32)
            s0 += Arow[j] * (1.0f - x[j]);
    }

    float sum = (s0 + s1) + (s2 + s3);
    #pragma unroll
    for (int off = 16; off > 0; off >>= 1)
        sum += __shfl_xor_sync(0xFFFFFFFFu, sum, off);

    if (lane == 0) warp_sum[warp] = sum;
    __syncthreads();

    if (warp == 0) {
        float v = (lane < WARPS_PER_BLOCK) ? warp_sum[lane] : 0.0f;
        #pragma unroll
        for (int off = 4; off > 0; off >>= 1)
            v += __shfl_xor_sync(0xFFFFFFFFu, v, off);
        if (lane == 0)
            out[row] = 0.1f * x[row] * v;
    }
}

extern "C" void kernel_launch(void* const* d_in, const int* in_sizes, int n_in,
                              void* d_out, int out_size)
{
    // metadata order: t (unused), x [n], A [n*n]
    const float* x = (const float*)d_in[1];
    const float* A = (const float*)d_in[2];
    float* out     = (float*)d_out;
    const int n    = in_sizes[1];

    // seg_len: multiple of 8 so segment bases stay 32B-aligned
    int seg_len = (n + WARPS_PER_BLOCK - 1) / WARPS_PER_BLOCK;
    seg_len = (seg_len + 7) & ~7;

    epidemic_matvec_kernel<<<n, THREADS>>>(x, A, out, n, seg_len);
}

// round 14
// speedup vs baseline: 1.1068x; 1.1068x over previous
#include <cuda_runtime.h>
#include <cuda_bf16.h>
#include <cstdint>

// out[i] = 0.1 * x[i] * sum_j A[i][j] * (1 - x[j])
// HBM-bound fp32 matvec. A (1 GiB) streamed once with evict-first LDG.128.
// K-split SEG=8: one warp per (row, 1/8-row segment) -> 8 KB tasks
// (proven sweet spot), 16384 blocks, independent warp exits + atomicAdd.
// Zero-init kernel overlapped with the matvec via PDL: matvec launches
// programmatically and only grid-dep-syncs right before its atomics.

#define WARPS_PER_BLOCK 8
#define THREADS (WARPS_PER_BLOCK * 32)
#define SEG 8

__global__ void init_out_kernel(float* __restrict__ out, int n)
{
    int i = blockIdx.x * blockDim.x + threadIdx.x;
    if (i < n) out[i] = 0.0f;
    cudaTriggerProgrammaticLaunchCompletion();
}

__global__ void __launch_bounds__(THREADS)
epidemic_matvec_kernel(const float* __restrict__ x,
                       const float* __restrict__ A,
                       float* __restrict__ out,
                       int n, int seg_len)
{
    const int tid    = threadIdx.x;
    const int lane   = tid & 31;
    const int warpId = blockIdx.x * WARPS_PER_BLOCK + (tid >> 5);
    if (warpId >= n * SEG) return;

    const int row = warpId >> 3;        // warpId / SEG
    const int seg = warpId & (SEG - 1); // warpId % SEG
    const int j0  = seg * seg_len;
    const int j1  = min(n, j0 + seg_len);
    if (j0 >= n) return;

    const float* __restrict__ Arow = A + (size_t)row * (size_t)n;

    float s0 = 0.0f, s1 = 0.0f, s2 = 0.0f, s3 = 0.0f;

    if ((n & 3) == 0) {
        // seg_len is a multiple of 8 -> segment bases stay 32B-aligned
        const float4* __restrict__ A4 = reinterpret_cast<const float4*>(Arow + j0);
        const float4* __restrict__ x4 = reinterpret_cast<const float4*>(x + j0);
        const int nv = (j1 - j0) >> 2;

        int k = lane;
        // Front-batch 4 independent streaming LDG.128 on A (MLP=4).
        for (; k + 96 < nv; k += 128) {
            float4 a0 = __ldcs(&A4[k]);
            float4 a1 = __ldcs(&A4[k + 32]);
            float4 a2 = __ldcs(&A4[k + 64]);
            float4 a3 = __ldcs(&A4[k + 96]);
            float4 b0 = x4[k];
            float4 b1 = x4[k + 32];
            float4 b2 = x4[k + 64];
            float4 b3 = x4[k + 96];
            s0 += a0.x * (1.0f - b0.x) + a0.y * (1.0f - b0.y)
                + a0.z * (1.0f - b0.z) + a0.w * (1.0f - b0.w);
            s1 += a1.x * (1.0f - b1.x) + a1.y * (1.0f - b1.y)
                + a1.z * (1.0f - b1.z) + a1.w * (1.0f - b1.w);
            s2 += a2.x * (1.0f - b2.x) + a2.y * (1.0f - b2.y)
                + a2.z * (1.0f - b2.z) + a2.w * (1.0f - b2.w);
            s3 += a3.x * (1.0f - b3.x) + a3.y * (1.0f - b3.y)
                + a3.z * (1.0f - b3.z) + a3.w * (1.0f - b3.w);
        }
        for (; k < nv; k += 32) {
            float4 a0 = __ldcs(&A4[k]);
            float4 b0 = x4[k];
            s0 += a0.x * (1.0f - b0.x) + a0.y * (1.0f - b0.y)
                + a0.z * (1.0f - b0.z) + a0.w * (1.0f - b0.w);
        }
        // scalar remainder within segment
        for (int j = j0 + (nv << 2) + lane; j < j1; j += 32)
            s0 += Arow[j] * (1.0f - x[j]);
    } else {
        // general scalar fallback
        for (int j = j0 + lane; j < j1; j += 32)
            s0 += Arow[j] * (1.0f - x[j]);
    }

    float sum = (s0 + s1) + (s2 + s3);
    #pragma unroll
    for (int off = 16; off > 0; off >>= 1)
        sum += __shfl_xor_sync(0xFFFFFFFFu, sum, off);

    if (lane == 0) {
        // Ensure the init kernel (zeroing out[]) has completed before the
        // first read-modify-write of out. All streaming work above ran
        // concurrently with init under PDL.
        cudaGridDependencySynchronize();
        atomicAdd(&out[row], 0.1f * x[row] * sum);
    }
}

extern "C" void kernel_launch(void* const* d_in, const int* in_sizes, int n_in,
                              void* d_out, int out_size)
{
    // metadata order: t (unused), x [n], A [n*n]
    const float* x = (const float*)d_in[1];
    const float* A = (const float*)d_in[2];
    float* out     = (float*)d_out;
    const int n    = in_sizes[1];

    // zero the accumulator output
    init_out_kernel<<<(n + 255) / 256, 256>>>(out, n);

    // seg_len: multiple of 8 so segment bases stay 32B-aligned
    int seg_len = (n + SEG - 1) / SEG;
    seg_len = (seg_len + 7) & ~7;

    const long long total_warps = (long long)n * SEG;
    const int blocks = (int)((total_warps + WARPS_PER_BLOCK - 1) / WARPS_PER_BLOCK);

    // Launch the matvec with programmatic stream serialization so it can
    // begin streaming A while init_out_kernel drains; ordering for the
    // atomics is enforced in-kernel via cudaGridDependencySynchronize().
    cudaLaunchConfig_t cfg = {};
    cfg.gridDim  = dim3((unsigned)blocks, 1, 1);
    cfg.blockDim = dim3(THREADS, 1, 1);
    cfg.dynamicSmemBytes = 0;
    cfg.stream = 0;
    cudaLaunchAttribute attrs[1];
    attrs[0].id = cudaLaunchAttributeProgrammaticStreamSerialization;
    attrs[0].val.programmaticStreamSerializationAllowed = 1;
    cfg.attrs = attrs;
    cfg.numAttrs = 1;

    cudaLaunchKernelEx(&cfg, epidemic_matvec_kernel, x, A, out, n, seg_len);
}